// round 7
// baseline (speedup 1.0000x reference)
#include <cuda_runtime.h>

// SSIM loss, 48 images of 512x512 f32, single fused kernel.
// Separable 11-tap Gaussian blur via shared-memory h+v passes.
// Packed fp32x2 (FFMA2): (mu1,mu2) and (E11,E22) pack field pairs;
// E12 packs output pairs with shifted weight pairs.
// Last block (atomic counter) performs the final global reduction.

static constexpr int NIMG = 48;
static constexpr int S    = 512;
static constexpr int T    = 32;   // output tile (T x T)
static constexpr int RIN  = 42;   // input tile rows (T + 10)
static constexpr int PIN  = 49;   // sPT pitch in float2
static constexpr int PH   = 33;   // sHmu/sHe pitch (floats2)
static constexpr int PH12 = 34;   // sH12 pitch (floats, even -> STS.64 aligned)
static constexpr int GRID = NIMG * 256;

__device__ float g_slots[GRID];
__device__ int   g_count = 0;     // reset by last block each invocation

static __device__ constexpr float W[11] = {
    0.00102838f, 0.00759876f, 0.03600077f, 0.10936066f, 0.21300549f,
    0.26601165f,
    0.21300549f, 0.10936066f, 0.03600077f, 0.00759876f, 0.00102838f
};
__host__ __device__ constexpr float WZ(int d) {
    return (d >= 0 && d < 11) ? W[d] : 0.0f;
}

__device__ __forceinline__ void ffma2(unsigned long long& d,
                                      unsigned long long a,
                                      unsigned long long b) {
    asm("fma.rn.f32x2 %0, %1, %2, %0;" : "+l"(d) : "l"(a), "l"(b));
}
__device__ __forceinline__ unsigned long long mul2(unsigned long long a,
                                                   unsigned long long b) {
    unsigned long long d;
    asm("mul.rn.f32x2 %0, %1, %2;" : "=l"(d) : "l"(a), "l"(b));
    return d;
}
__device__ __forceinline__ unsigned long long packf2(float lo, float hi) {
    unsigned long long d;
    asm("mov.b64 %0, {%1, %2};" : "=l"(d) : "f"(lo), "f"(hi));
    return d;
}
__device__ __forceinline__ void unpackf2(unsigned long long v, float& lo, float& hi) {
    asm("mov.b64 {%0, %1}, %2;" : "=f"(lo), "=f"(hi) : "l"(v));
}

__global__ void __launch_bounds__(256) ssim_kernel(
    const float* __restrict__ pred, const float* __restrict__ targ,
    float* __restrict__ out)
{
    __shared__ float2 sPT [RIN * PIN];   // interleaved (p, t)
    __shared__ float2 sHmu[RIN * PH];    // (blur_h p, blur_h t)
    __shared__ float2 sHe [RIN * PH];    // (blur_h p^2, blur_h t^2)
    __shared__ float  sH12[RIN * PH12];  // blur_h (p*t)
    __shared__ float  red[8];
    __shared__ int    isLast;

    const int tid  = threadIdx.x;
    const int img  = blockIdx.x >> 8;
    const int tile = blockIdx.x & 255;
    const int oy   = (tile >> 4) * T;
    const int ox   = (tile & 15) * T;

    const float* P = pred + img * (S * S);
    const float* Q = targ + img * (S * S);

    unsigned long long ww[11];   // duplicated weights (W[k], W[k])
    unsigned long long wp[12];   // shifted pairs (W[d], W[d-1])
#pragma unroll
    for (int k = 0; k < 11; ++k) ww[k] = packf2(W[k], W[k]);
#pragma unroll
    for (int d = 0; d < 12; ++d) wp[d] = packf2(WZ(d), WZ(d - 1));

    // ---- load: 42 rows x 12 float4 per field; interleave into sPT ----
    for (int i = tid; i < RIN * 12; i += 256) {
        int r   = i / 12;
        int q   = i - r * 12;
        int gy  = oy + r - 5;
        int gx0 = ox + q * 4 - 8;
        float4 p4, t4;
        if (gy >= 0 && gy < S && gx0 >= 0 && gx0 + 3 < S) {
            p4 = *reinterpret_cast<const float4*>(P + gy * S + gx0);
            t4 = *reinterpret_cast<const float4*>(Q + gy * S + gx0);
        } else {
            float pv[4], tv[4];
#pragma unroll
            for (int j = 0; j < 4; ++j) {
                int gx = gx0 + j;
                bool ok = (gy >= 0 && gy < S && gx >= 0 && gx < S);
                pv[j] = ok ? __ldg(P + gy * S + gx) : 0.f;
                tv[j] = ok ? __ldg(Q + gy * S + gx) : 0.f;
            }
            p4 = make_float4(pv[0], pv[1], pv[2], pv[3]);
            t4 = make_float4(tv[0], tv[1], tv[2], tv[3]);
        }
        float2* dst = sPT + r * PIN + q * 4;
        dst[0] = make_float2(p4.x, t4.x);
        dst[1] = make_float2(p4.y, t4.y);
        dst[2] = make_float2(p4.z, t4.z);
        dst[3] = make_float2(p4.w, t4.w);
    }
    __syncthreads();

    // ---- horizontal pass: 42 rows x 8 groups of 4 output cols ----
    for (int it = tid; it < RIN * 8; it += 256) {
        int r = it % RIN;
        int g = it / RIN;
        int base = r * PIN + g * 4 + 3;
        unsigned long long accA[4] = {0, 0, 0, 0};   // (mu1,mu2) per col
        unsigned long long accB[4] = {0, 0, 0, 0};   // (E11,E22) per col
        unsigned long long accC[2] = {0, 0};         // E12 packed col-pairs
#pragma unroll
        for (int k = 0; k < 14; ++k) {
            unsigned long long v =
                *reinterpret_cast<const unsigned long long*>(&sPT[base + k]);
            float p, t;
            unpackf2(v, p, t);
            unsigned long long sq  = mul2(v, v);
            float pt = p * t;
            unsigned long long pt2 = packf2(pt, pt);
#pragma unroll
            for (int j = 0; j < 4; ++j) {
                int w = k - j;
                if (w >= 0 && w < 11) {
                    ffma2(accA[j], v,  ww[w]);
                    ffma2(accB[j], sq, ww[w]);
                }
            }
#pragma unroll
            for (int h = 0; h < 2; ++h) {
                int d = k - 2 * h;
                if (d >= 0 && d < 12) ffma2(accC[h], pt2, wp[d]);
            }
        }
        int ob = r * PH + g * 4;
#pragma unroll
        for (int j = 0; j < 4; ++j) {
            *reinterpret_cast<unsigned long long*>(&sHmu[ob + j]) = accA[j];
            *reinterpret_cast<unsigned long long*>(&sHe [ob + j]) = accB[j];
        }
        int oc = r * PH12 + g * 4;
        *reinterpret_cast<unsigned long long*>(&sH12[oc])     = accC[0];
        *reinterpret_cast<unsigned long long*>(&sH12[oc + 2]) = accC[1];
    }
    __syncthreads();

    // ---- vertical pass + SSIM: each thread 4 rows, 1 col ----
    const int x  = tid & 31;
    const int y0 = (tid >> 5) * 4;
    unsigned long long M[4]  = {0, 0, 0, 0};
    unsigned long long E[4]  = {0, 0, 0, 0};
    unsigned long long C2[2] = {0, 0};       // E12 packed row-pairs
#pragma unroll
    for (int k = 0; k < 14; ++k) {
        int rr = y0 + k;
        unsigned long long vm =
            *reinterpret_cast<const unsigned long long*>(&sHmu[rr * PH + x]);
        unsigned long long ve =
            *reinterpret_cast<const unsigned long long*>(&sHe[rr * PH + x]);
        float v12 = sH12[rr * PH12 + x];
        unsigned long long v12d = packf2(v12, v12);
#pragma unroll
        for (int j = 0; j < 4; ++j) {
            int w = k - j;
            if (w >= 0 && w < 11) {
                ffma2(M[j], vm, ww[w]);
                ffma2(E[j], ve, ww[w]);
            }
        }
#pragma unroll
        for (int h = 0; h < 2; ++h) {
            int d = k - 2 * h;
            if (d >= 0 && d < 12) ffma2(C2[h], v12d, wp[d]);
        }
    }

    const float C1 = 1e-4f, C2c = 9e-4f, EPSV = 1e-8f;
    float e12v[4];
    unpackf2(C2[0], e12v[0], e12v[1]);
    unpackf2(C2[1], e12v[2], e12v[3]);
    float local = 0.f;
#pragma unroll
    for (int j = 0; j < 4; ++j) {
        float m1, m2, e11, e22;
        unpackf2(M[j], m1, m2);
        unpackf2(E[j], e11, e22);
        float a2 = m1 * m1, b2 = m2 * m2, ab = m1 * m2;
        float s1  = e11 - a2;
        float s2  = e22 - b2;
        float s12 = e12v[j] - ab;
        float num = (2.f * ab + C1) * (2.f * s12 + C2c);
        float den = fmaf(a2 + b2 + C1, s1 + s2 + C2c, EPSV);
        local += __fdividef(num, den);
    }

    // ---- block reduction ----
#pragma unroll
    for (int o = 16; o > 0; o >>= 1)
        local += __shfl_down_sync(0xffffffffu, local, o);
    if ((tid & 31) == 0) red[tid >> 5] = local;
    __syncthreads();
    if (tid == 0) {
        float s = 0.f;
#pragma unroll
        for (int i = 0; i < 8; ++i) s += red[i];
        g_slots[blockIdx.x] = s;
        __threadfence();
        int old = atomicAdd(&g_count, 1);
        isLast = (old == GRID - 1);
    }
    __syncthreads();

    // ---- last block: final reduction over all block partials ----
    if (isLast) {
        __shared__ double sd[256];
        double acc = 0.0;
        for (int i = tid; i < GRID; i += 256)
            acc += (double)__ldcg(&g_slots[i]);
        sd[tid] = acc;
        __syncthreads();
        for (int s = 128; s > 0; s >>= 1) {
            if (tid < s) sd[tid] += sd[tid + s];
            __syncthreads();
        }
        if (tid == 0) {
            out[0] = (float)(1.0 - sd[0] / ((double)NIMG * S * S));
            g_count = 0;   // reset for next invocation / graph replay
        }
    }
}

extern "C" void kernel_launch(void* const* d_in, const int* in_sizes, int n_in,
                              void* d_out, int out_size)
{
    const float* pred = (const float*)d_in[0];
    const float* targ = (const float*)d_in[1];
    float* out = (float*)d_out;

    ssim_kernel<<<GRID, 256>>>(pred, targ, out);
}